// round 11
// baseline (speedup 1.0000x reference)
#include <cuda_runtime.h>

#define BT   8192   // B*T
#define DMM  1024
#define HN   16
#define DHD  64
#define TSEQ 2048
#define BATCH 4

// Scratch: tf32-RNA bit patterns.
__device__ unsigned g_x1c[BT * DMM];
__device__ unsigned g_x2c[BT * DMM];
__device__ unsigned g_wqt[DMM * DMM];        // Wq^T  [N][K]
__device__ unsigned g_wkvt[2 * DMM * DMM];   // Wkv^T [N][K]
__device__ unsigned g_wot[DMM * DMM];        // Wo^T  [N][K]
__device__ unsigned g_q[BT * DMM];           // Q proj (bits, pre-scaled 1/8)
__device__ unsigned g_kv[BT * 2 * DMM];      // KV proj (bits)
__device__ unsigned g_attn[BT * DMM];        // attention out (bits)

__device__ __forceinline__ void cp16(unsigned* smem, const void* gmem) {
    unsigned s = (unsigned)__cvta_generic_to_shared(smem);
    asm volatile("cp.async.cg.shared.global [%0], [%1], 16;\n" :: "r"(s), "l"(gmem));
}
__device__ __forceinline__ void cp_commit() {
    asm volatile("cp.async.commit_group;\n" ::: "memory");
}
__device__ __forceinline__ void cp_wait1() {
    asm volatile("cp.async.wait_group 1;\n" ::: "memory");
}
__device__ __forceinline__ void cp_wait0() {
    asm volatile("cp.async.wait_group 0;\n" ::: "memory");
}

__device__ __forceinline__ unsigned f2tf(float x) {
    unsigned r;
    asm("cvt.rna.tf32.f32 %0, %1;" : "=r"(r) : "f"(x));
    return r;
}

__device__ __forceinline__ void mma_tf32(float* d, const unsigned* a, const unsigned* b) {
    asm volatile(
        "mma.sync.aligned.m16n8k8.row.col.f32.tf32.tf32.f32 "
        "{%0,%1,%2,%3}, {%4,%5,%6,%7}, {%8,%9}, {%0,%1,%2,%3};\n"
        : "+f"(d[0]), "+f"(d[1]), "+f"(d[2]), "+f"(d[3])
        : "r"(a[0]), "r"(a[1]), "r"(a[2]), "r"(a[3]),
          "r"(b[0]), "r"(b[1]));
}

__device__ __forceinline__ void ldsm4(unsigned r[4], const unsigned* p) {
    unsigned a = (unsigned)__cvta_generic_to_shared(p);
    asm volatile("ldmatrix.sync.aligned.m8n8.x4.shared.b16 {%0,%1,%2,%3}, [%4];"
        : "=r"(r[0]), "=r"(r[1]), "=r"(r[2]), "=r"(r[3]) : "r"(a));
}

// ----------------------------------------------------------------------------
// Prep kernels
// ----------------------------------------------------------------------------
__global__ __launch_bounds__(256) void cvt_kernel(
    const float4* __restrict__ src, uint4* __restrict__ dst, int n4)
{
    int i = blockIdx.x * 256 + threadIdx.x;
    if (i < n4) {
        float4 v = src[i];
        dst[i] = make_uint4(f2tf(v.x), f2tf(v.y), f2tf(v.z), f2tf(v.w));
    }
}

__global__ __launch_bounds__(256) void transpose_cvt_kernel(
    const float* __restrict__ W, unsigned* __restrict__ Wt, int K, int N)
{
    __shared__ unsigned t[32][33];
    int bn = blockIdx.x * 32, bk = blockIdx.y * 32;
    int tx = threadIdx.x & 31, ty = threadIdx.x >> 5;
    #pragma unroll
    for (int i = ty; i < 32; i += 8)
        t[tx][i] = f2tf(W[(size_t)(bk + i) * N + bn + tx]);
    __syncthreads();
    #pragma unroll
    for (int i = ty; i < 32; i += 8)
        Wt[(size_t)(bn + i) * K + bk + tx] = t[i][tx];
}

// ----------------------------------------------------------------------------
// TF32 GEMM: CTA 128x256, BK=16, 8 warps (2x4), warp tile 64x64.
// A[m][k] bits; Bt[n][k] bits. Both smem tiles stride 20 (LDSM conflict-free).
// ----------------------------------------------------------------------------
#define LD20 20

__global__ __launch_bounds__(256, 1) void tgemm_kernel(
    const unsigned* __restrict__ A, const unsigned* __restrict__ Bt,
    float* __restrict__ C, int M, int N, int K, const float* __restrict__ bias,
    float oscale, int convert)
{
    __shared__ unsigned As[2][128 * LD20];
    __shared__ unsigned Bs[2][256 * LD20];
    int tid = threadIdx.x;
    int lane = tid & 31, wid = tid >> 5;
    int g = lane >> 2, tig = lane & 3;
    int warpM = wid & 1, warpN = wid >> 1;   // 2 x 4

    int mat = lane >> 3, l7 = lane & 7;
    int mrow = (mat & 1) * 8 + l7, mk4 = (mat >> 1) * 4;   // A-operand LDSM map
    int nrow = (mat >> 1) * 8 + l7, nk4 = (mat & 1) * 4;   // B-operand LDSM map

    const unsigned* Ap = A + (size_t)blockIdx.y * 128 * K;
    const unsigned* Bp = Bt + (size_t)blockIdx.x * 256 * K;

    float acc[4][8][4] = {};   // [mi][ni][frag]

    auto issueTile = [&](int k0, int st) {
        #pragma unroll
        for (int i2 = 0; i2 < 2; i2++) {      // A: 512 vec4
            int v = tid + i2 * 256;
            cp16(&As[st][(v >> 2) * LD20 + (v & 3) * 4],
                 Ap + (size_t)(v >> 2) * K + k0 + (v & 3) * 4);
        }
        #pragma unroll
        for (int i2 = 0; i2 < 4; i2++) {      // B: 1024 vec4
            int v = tid + i2 * 256;
            cp16(&Bs[st][(v >> 2) * LD20 + (v & 3) * 4],
                 Bp + (size_t)(v >> 2) * K + k0 + (v & 3) * 4);
        }
        cp_commit();
    };

    int NIT = K >> 4;
    issueTile(0, 0);

    for (int it = 0; it < NIT; it++) {
        int st = it & 1;
        if (it + 1 < NIT) { issueTile((it + 1) << 4, st ^ 1); cp_wait1(); }
        else              { cp_wait0(); }
        __syncthreads();

        #pragma unroll
        for (int ks = 0; ks < 2; ks++) {
            int kk = ks * 8;
            unsigned af[4][4], bf[4][4];
            #pragma unroll
            for (int mi = 0; mi < 4; mi++)
                ldsm4(af[mi], &As[st][(warpM * 64 + mi * 16 + mrow) * LD20 + kk + mk4]);
            #pragma unroll
            for (int nip = 0; nip < 4; nip++)
                ldsm4(bf[nip], &Bs[st][(warpN * 64 + nip * 16 + nrow) * LD20 + kk + nk4]);
            #pragma unroll
            for (int mi = 0; mi < 4; mi++)
                #pragma unroll
                for (int ni = 0; ni < 8; ni++)
                    mma_tf32(acc[mi][ni], af[mi], &bf[ni >> 1][(ni & 1) * 2]);
        }
        __syncthreads();
    }

    #pragma unroll
    for (int mi = 0; mi < 4; mi++) {
        size_t r0 = (size_t)blockIdx.y * 128 + warpM * 64 + mi * 16 + g;
        #pragma unroll
        for (int ni = 0; ni < 8; ni++) {
            int col = blockIdx.x * 256 + warpN * 64 + ni * 8 + tig * 2;
            if (convert) {
                *(uint2*)((unsigned*)C + r0 * N + col) =
                    make_uint2(f2tf(acc[mi][ni][0] * oscale), f2tf(acc[mi][ni][1] * oscale));
                *(uint2*)((unsigned*)C + (r0 + 8) * N + col) =
                    make_uint2(f2tf(acc[mi][ni][2] * oscale), f2tf(acc[mi][ni][3] * oscale));
            } else {
                float b0 = bias[col], b1 = bias[col + 1];
                *(float2*)(C + r0 * N + col) =
                    make_float2(acc[mi][ni][0] + b0, acc[mi][ni][1] + b1);
                *(float2*)(C + (r0 + 8) * N + col) =
                    make_float2(acc[mi][ni][2] + b0, acc[mi][ni][3] + b1);
            }
        }
    }
}

// ----------------------------------------------------------------------------
// Flash attention: BQ=256 queries/CTA, 8 warps, warp owns 32 rows (2 m-tiles).
// K/V reads amortized over 2x rows vs R10. Inputs pre-converted tf32 bits.
// ----------------------------------------------------------------------------
#define BQ 256
#define BK 64
#define LQ 68
#define LK 68
#define LV 72
#define LP 68

__global__ __launch_bounds__(256, 1) void fattn_kernel(
    const unsigned* __restrict__ Q, const unsigned* __restrict__ KV,
    const float* __restrict__ mask, unsigned* __restrict__ O)
{
    extern __shared__ unsigned sm[];
    unsigned* Qs = sm;                          // [256][68]
    unsigned* Ps = Qs + BQ * LQ;                // [256][68]
    unsigned* Ks = Ps + BQ * LP;                // [2][64][68]
    unsigned* Vs = Ks + 2 * BK * LK;            // [2][64][72]
    float*    Msk = (float*)(Vs + 2 * BK * LV); // [2048]

    int qb = blockIdx.x, h = blockIdx.y, b = blockIdx.z;
    int tid = threadIdx.x;
    int lane = tid & 31, wid = tid >> 5;
    int g = lane >> 2, tig = lane & 3;
    int warpRow = wid * 32;

    int mat = lane >> 3, l7 = lane & 7;
    int mrow = (mat & 1) * 8 + l7, mk4 = (mat >> 1) * 4;
    int nrow = (mat >> 1) * 8 + l7, nk4 = (mat & 1) * 4;

    const unsigned* KVbase = KV + (size_t)b * TSEQ * 2048 + h * 128;

    auto issueKV = [&](int kt, int st) {
        unsigned* Kst = Ks + st * BK * LK;
        unsigned* Vst = Vs + st * BK * LV;
        const unsigned* base = KVbase + (size_t)kt * BK * 2048;
        #pragma unroll
        for (int i2 = 0; i2 < 4; i2++) {
            int i = tid + i2 * 256;
            int row = i >> 4, c4 = (i & 15) << 2;
            const unsigned* kp = base + (size_t)row * 2048 + c4;
            cp16(&Kst[row * LK + c4], kp);
            cp16(&Vst[row * LV + c4], kp + 64);
        }
        cp_commit();
    };

    // Q tile (256 rows) + mask via cp.async, first commit group with KV0
    {
        const unsigned* Qbase = Q + (size_t)(b * TSEQ + qb * BQ) * DMM + h * DHD;
        #pragma unroll
        for (int i2 = 0; i2 < 16; i2++) {
            int i = tid + i2 * 256;
            int row = i >> 4, c4 = (i & 15) << 2;
            cp16(&Qs[row * LQ + c4], Qbase + (size_t)row * DMM + c4);
        }
        #pragma unroll
        for (int i2 = 0; i2 < 2; i2++) {
            int i = tid + i2 * 256;
            cp16((unsigned*)&Msk[i * 4], mask + (size_t)b * TSEQ + i * 4);
        }
    }
    issueKV(0, 0);

    float acc[2][8][4] = {};
    float m0[2] = {-1e30f, -1e30f}, m1[2] = {-1e30f, -1e30f};
    float l0[2] = {0.f, 0.f}, l1[2] = {0.f, 0.f};
    const int NT = TSEQ / BK;

    for (int kt = 0; kt < NT; kt++) {
        int st = kt & 1;
        if (kt + 1 < NT) { issueKV(kt + 1, st ^ 1); cp_wait1(); }
        else             { cp_wait0(); }
        __syncthreads();

        unsigned* Kst = Ks + st * BK * LK;
        unsigned* Vst = Vs + st * BK * LV;

        // S = Q K^T  (warp: 32 x 64)
        float s[2][8][4] = {};
        #pragma unroll
        for (int ks = 0; ks < 8; ks++) {
            int kk = ks * 8;
            unsigned af[2][4], bk4[4][4];
            ldsm4(af[0], &Qs[(warpRow + mrow) * LQ + kk + mk4]);
            ldsm4(af[1], &Qs[(warpRow + 16 + mrow) * LQ + kk + mk4]);
            #pragma unroll
            for (int ntp = 0; ntp < 4; ntp++)
                ldsm4(bk4[ntp], &Kst[(ntp * 16 + nrow) * LK + kk + nk4]);
            #pragma unroll
            for (int nt = 0; nt < 8; nt++) {
                mma_tf32(s[0][nt], af[0], &bk4[nt >> 1][(nt & 1) * 2]);
                mma_tf32(s[1][nt], af[1], &bk4[nt >> 1][(nt & 1) * 2]);
            }
        }

        // Mask
        #pragma unroll
        for (int nt = 0; nt < 8; nt++) {
            int c0 = kt * BK + nt * 8 + tig * 2;
            bool z0 = (Msk[c0] == 0.f), z1 = (Msk[c0 + 1] == 0.f);
            #pragma unroll
            for (int mi = 0; mi < 2; mi++) {
                if (z0) { s[mi][nt][0] = -1e30f; s[mi][nt][2] = -1e30f; }
                if (z1) { s[mi][nt][1] = -1e30f; s[mi][nt][3] = -1e30f; }
            }
        }

        // Online softmax per mi (rows warpRow+mi*16+g, +8)
        #pragma unroll
        for (int mi = 0; mi < 2; mi++) {
            float mx0 = -1e30f, mx1 = -1e30f;
            #pragma unroll
            for (int nt = 0; nt < 8; nt++) {
                mx0 = fmaxf(mx0, fmaxf(s[mi][nt][0], s[mi][nt][1]));
                mx1 = fmaxf(mx1, fmaxf(s[mi][nt][2], s[mi][nt][3]));
            }
            #pragma unroll
            for (int o = 1; o < 4; o <<= 1) {
                mx0 = fmaxf(mx0, __shfl_xor_sync(0xffffffffu, mx0, o));
                mx1 = fmaxf(mx1, __shfl_xor_sync(0xffffffffu, mx1, o));
            }
            float mn0 = fmaxf(m0[mi], mx0), mn1 = fmaxf(m1[mi], mx1);
            float cr0 = __expf(m0[mi] - mn0), cr1 = __expf(m1[mi] - mn1);
            float rs0 = 0.f, rs1 = 0.f;
            #pragma unroll
            for (int nt = 0; nt < 8; nt++) {
                s[mi][nt][0] = __expf(s[mi][nt][0] - mn0); rs0 += s[mi][nt][0];
                s[mi][nt][1] = __expf(s[mi][nt][1] - mn0); rs0 += s[mi][nt][1];
                s[mi][nt][2] = __expf(s[mi][nt][2] - mn1); rs1 += s[mi][nt][2];
                s[mi][nt][3] = __expf(s[mi][nt][3] - mn1); rs1 += s[mi][nt][3];
            }
            #pragma unroll
            for (int o = 1; o < 4; o <<= 1) {
                rs0 += __shfl_xor_sync(0xffffffffu, rs0, o);
                rs1 += __shfl_xor_sync(0xffffffffu, rs1, o);
            }
            l0[mi] = l0[mi] * cr0 + rs0;  m0[mi] = mn0;
            l1[mi] = l1[mi] * cr1 + rs1;  m1[mi] = mn1;
            #pragma unroll
            for (int nt = 0; nt < 8; nt++) {
                acc[mi][nt][0] *= cr0; acc[mi][nt][1] *= cr0;
                acc[mi][nt][2] *= cr1; acc[mi][nt][3] *= cr1;
            }
            // P -> smem (RNA bits); warp-private rows
            int rbase = warpRow + mi * 16;
            #pragma unroll
            for (int nt = 0; nt < 8; nt++) {
                int colb = nt * 8 + tig * 2;
                *(uint2*)&Ps[(rbase + g) * LP + colb] =
                    make_uint2(f2tf(s[mi][nt][0]), f2tf(s[mi][nt][1]));
                *(uint2*)&Ps[(rbase + g + 8) * LP + colb] =
                    make_uint2(f2tf(s[mi][nt][2]), f2tf(s[mi][nt][3]));
            }
        }
        __syncwarp();

        // O += P V  — V bf loaded once per (ks, nt), reused for both mi
        #pragma unroll
        for (int ks = 0; ks < 8; ks++) {
            int kk = ks * 8;
            unsigned af[2][4];
            ldsm4(af[0], &Ps[(warpRow + mrow) * LP + kk + mk4]);
            ldsm4(af[1], &Ps[(warpRow + 16 + mrow) * LP + kk + mk4]);
            #pragma unroll
            for (int nt = 0; nt < 8; nt++) {
                unsigned bf[2];
                int c = nt * 8 + g;
                bf[0] = Vst[(kk + tig) * LV + c];
                bf[1] = Vst[(kk + tig + 4) * LV + c];
                mma_tf32(acc[0][nt], af[0], bf);
                mma_tf32(acc[1][nt], af[1], bf);
            }
        }
        __syncthreads();
    }

    // Epilogue: normalize, RNA-convert, store bits
    #pragma unroll
    for (int mi = 0; mi < 2; mi++) {
        float inv0 = 1.f / l0[mi], inv1 = 1.f / l1[mi];
        size_t row0 = (size_t)(b * TSEQ + qb * BQ + warpRow + mi * 16 + g);
        #pragma unroll
        for (int nt = 0; nt < 8; nt++) {
            int col = h * DHD + nt * 8 + tig * 2;
            *(uint2*)(O + row0 * DMM + col) =
                make_uint2(f2tf(acc[mi][nt][0] * inv0), f2tf(acc[mi][nt][1] * inv0));
            *(uint2*)(O + (row0 + 8) * DMM + col) =
                make_uint2(f2tf(acc[mi][nt][2] * inv1), f2tf(acc[mi][nt][3] * inv1));
        }
    }
}

// ----------------------------------------------------------------------------
extern "C" void kernel_launch(void* const* d_in, const int* in_sizes, int n_in,
                              void* d_out, int out_size)
{
    const float* x1   = (const float*)d_in[0];
    const float* x2   = (const float*)d_in[1];
    const float* mask = (const float*)d_in[2];
    const float* Wq   = (const float*)d_in[3];
    const float* Wkv  = (const float*)d_in[4];
    const float* Wo   = (const float*)d_in[5];
    const float* bo   = (const float*)d_in[6];
    float* out = (float*)d_out;

    unsigned *x1c, *x2c, *wqt, *wkvt, *wot, *q, *kv, *attn;
    cudaGetSymbolAddress((void**)&x1c, g_x1c);
    cudaGetSymbolAddress((void**)&x2c, g_x2c);
    cudaGetSymbolAddress((void**)&wqt, g_wqt);
    cudaGetSymbolAddress((void**)&wkvt, g_wkvt);
    cudaGetSymbolAddress((void**)&wot, g_wot);
    cudaGetSymbolAddress((void**)&q, g_q);
    cudaGetSymbolAddress((void**)&kv, g_kv);
    cudaGetSymbolAddress((void**)&attn, g_attn);

    dim3 blk(256);
    cvt_kernel<<<BT * DMM / 1024, blk>>>((const float4*)x1, (uint4*)x1c, BT * DMM / 4);
    cvt_kernel<<<BT * DMM / 1024, blk>>>((const float4*)x2, (uint4*)x2c, BT * DMM / 4);
    transpose_cvt_kernel<<<dim3(DMM / 32, DMM / 32), blk>>>(Wq, wqt, DMM, DMM);
    transpose_cvt_kernel<<<dim3(2 * DMM / 32, DMM / 32), blk>>>(Wkv, wkvt, DMM, 2 * DMM);
    transpose_cvt_kernel<<<dim3(DMM / 32, DMM / 32), blk>>>(Wo, wot, DMM, DMM);

    // Projections (CTA 128x256)
    tgemm_kernel<<<dim3(DMM / 256, BT / 128), blk>>>(
        x1c, wqt, (float*)q, BT, DMM, DMM, nullptr, 0.125f, 1);
    tgemm_kernel<<<dim3(2 * DMM / 256, BT / 128), blk>>>(
        x2c, wkvt, (float*)kv, BT, 2 * DMM, DMM, nullptr, 1.0f, 1);

    int smem_bytes = (BQ * LQ + BQ * LP + 2 * BK * LK + 2 * BK * LV + TSEQ)
                     * (int)sizeof(unsigned);   // 219,136 B
    cudaFuncSetAttribute(fattn_kernel, cudaFuncAttributeMaxDynamicSharedMemorySize, smem_bytes);
    fattn_kernel<<<dim3(TSEQ / BQ, HN, BATCH), blk, smem_bytes>>>(q, kv, mask, attn);

    tgemm_kernel<<<dim3(DMM / 256, BT / 128), blk>>>(
        attn, wot, out, BT, DMM, DMM, bo, 1.0f, 0);
}

// round 14
// speedup vs baseline: 1.0108x; 1.0108x over previous
#include <cuda_runtime.h>

#define BT   8192   // B*T
#define DMM  1024
#define HN   16
#define DHD  64
#define TSEQ 2048
#define BATCH 4

// Scratch: tf32-RNA bit patterns (weights transposed; intermediates from epilogues)
__device__ unsigned g_wqt[DMM * DMM];        // Wq^T  [N][K]
__device__ unsigned g_wkvt[2 * DMM * DMM];   // Wkv^T [N][K]
__device__ unsigned g_wot[DMM * DMM];        // Wo^T  [N][K]
__device__ unsigned g_q[BT * DMM];           // Q proj (bits, pre-scaled 1/8)
__device__ unsigned g_kv[BT * 2 * DMM];      // KV proj (bits)
__device__ unsigned g_attn[BT * DMM];        // attention out (bits)

__device__ __forceinline__ void cp16(unsigned* smem, const void* gmem) {
    unsigned s = (unsigned)__cvta_generic_to_shared(smem);
    asm volatile("cp.async.cg.shared.global [%0], [%1], 16;\n" :: "r"(s), "l"(gmem));
}
__device__ __forceinline__ void cp_commit() {
    asm volatile("cp.async.commit_group;\n" ::: "memory");
}
__device__ __forceinline__ void cp_wait1() {
    asm volatile("cp.async.wait_group 1;\n" ::: "memory");
}
__device__ __forceinline__ void cp_wait0() {
    asm volatile("cp.async.wait_group 0;\n" ::: "memory");
}

__device__ __forceinline__ unsigned f2tf(float x) {   // RNA round to tf32
    unsigned r;
    asm("cvt.rna.tf32.f32 %0, %1;" : "=r"(r) : "f"(x));
    return r;
}
__device__ __forceinline__ unsigned u2tf(unsigned x) { // RNA on raw fp32 bits
    unsigned r;
    asm("cvt.rna.tf32.f32 %0, %1;" : "=r"(r) : "f"(__uint_as_float(x)));
    return r;
}

__device__ __forceinline__ void mma_tf32(float* d, const unsigned* a, const unsigned* b) {
    asm volatile(
        "mma.sync.aligned.m16n8k8.row.col.f32.tf32.tf32.f32 "
        "{%0,%1,%2,%3}, {%4,%5,%6,%7}, {%8,%9}, {%0,%1,%2,%3};\n"
        : "+f"(d[0]), "+f"(d[1]), "+f"(d[2]), "+f"(d[3])
        : "r"(a[0]), "r"(a[1]), "r"(a[2]), "r"(a[3]),
          "r"(b[0]), "r"(b[1]));
}

__device__ __forceinline__ void ldsm4(unsigned r[4], const unsigned* p) {
    unsigned a = (unsigned)__cvta_generic_to_shared(p);
    asm volatile("ldmatrix.sync.aligned.m8n8.x4.shared.b16 {%0,%1,%2,%3}, [%4];"
        : "=r"(r[0]), "=r"(r[1]), "=r"(r[2]), "=r"(r[3]) : "r"(a));
}

// ----------------------------------------------------------------------------
// Prep: transpose+cvt weights only (~16us total). Activations stay raw fp32;
// their RNA happens on A-fragments in registers inside the GEMM.
// ----------------------------------------------------------------------------
__global__ __launch_bounds__(256) void transpose_cvt_kernel(
    const float* __restrict__ W, unsigned* __restrict__ Wt, int K, int N)
{
    __shared__ unsigned t[32][33];
    int bn = blockIdx.x * 32, bk = blockIdx.y * 32;
    int tx = threadIdx.x & 31, ty = threadIdx.x >> 5;
    #pragma unroll
    for (int i = ty; i < 32; i += 8)
        t[tx][i] = f2tf(W[(size_t)(bk + i) * N + bn + tx]);
    __syncthreads();
    #pragma unroll
    for (int i = ty; i < 32; i += 8)
        Wt[(size_t)(bn + i) * K + bk + tx] = t[i][tx];
}

// ----------------------------------------------------------------------------
// TF32 GEMM (R10 structure): CTA 128x128, BK=16, 8 warps (2x4), warp 64x32.
// A[m][k]; Bt[n][k] pre-transposed pre-cvt'd. Both smem tiles stride 20
// (LDSM conflict-free). cp.async double-buffered.
// ACONV=1: A arrives as raw fp32 -> RNA-cvt the A-fragments after ldmatrix.
// ACONV=0: A already tf32 bits (from a converting epilogue).
// CONVERT=1: store RNA-tf32 bits of acc*oscale; else fp32 + bias.
// ----------------------------------------------------------------------------
#define LD20 20

template<int ACONV, int CONVERT>
__global__ __launch_bounds__(256, 2) void tgemm_kernel(
    const unsigned* __restrict__ A, const unsigned* __restrict__ Bt,
    float* __restrict__ C, int M, int N, int K, const float* __restrict__ bias,
    float oscale)
{
    __shared__ unsigned As[2][128 * LD20];
    __shared__ unsigned Bs[2][128 * LD20];
    int tid = threadIdx.x;
    int lane = tid & 31, wid = tid >> 5;
    int g = lane >> 2, tig = lane & 3;
    int warpM = wid & 1, warpN = wid >> 1;

    int mat = lane >> 3, l7 = lane & 7;
    int mrow = (mat & 1) * 8 + l7, mk4 = (mat >> 1) * 4;   // A-operand LDSM map
    int nrow = (mat >> 1) * 8 + l7, nk4 = (mat & 1) * 4;   // B-operand LDSM map

    const unsigned* Ap = A + (size_t)blockIdx.y * 128 * K;
    const unsigned* Bp = Bt + (size_t)blockIdx.x * 128 * K;

    float acc[4][4][4] = {};
    int av0 = tid, av1 = tid + 256;
    int r0v = av0 >> 2, c0v = (av0 & 3) * 4;
    int r1v = av1 >> 2, c1v = (av1 & 3) * 4;

    auto issueTile = [&](int k0, int st) {
        cp16(&As[st][r0v * LD20 + c0v], Ap + (size_t)r0v * K + k0 + c0v);
        cp16(&As[st][r1v * LD20 + c1v], Ap + (size_t)r1v * K + k0 + c1v);
        cp16(&Bs[st][r0v * LD20 + c0v], Bp + (size_t)r0v * K + k0 + c0v);
        cp16(&Bs[st][r1v * LD20 + c1v], Bp + (size_t)r1v * K + k0 + c1v);
        cp_commit();
    };

    int NIT = K >> 4;
    issueTile(0, 0);

    for (int it = 0; it < NIT; it++) {
        int st = it & 1;
        if (it + 1 < NIT) { issueTile((it + 1) << 4, st ^ 1); cp_wait1(); }
        else              { cp_wait0(); }
        __syncthreads();

        #pragma unroll
        for (int ks = 0; ks < 2; ks++) {
            int kk = ks * 8;
            unsigned af[4][4], bf[2][4];
            #pragma unroll
            for (int mi = 0; mi < 4; mi++) {
                ldsm4(af[mi], &As[st][(warpM * 64 + mi * 16 + mrow) * LD20 + kk + mk4]);
                if (ACONV) {
                    #pragma unroll
                    for (int j = 0; j < 4; j++) af[mi][j] = u2tf(af[mi][j]);
                }
            }
            #pragma unroll
            for (int nip = 0; nip < 2; nip++)
                ldsm4(bf[nip], &Bs[st][(warpN * 32 + nip * 16 + nrow) * LD20 + kk + nk4]);
            #pragma unroll
            for (int mi = 0; mi < 4; mi++)
                #pragma unroll
                for (int ni = 0; ni < 4; ni++)
                    mma_tf32(acc[mi][ni], af[mi], &bf[ni >> 1][(ni & 1) * 2]);
        }
        __syncthreads();
    }

    #pragma unroll
    for (int mi = 0; mi < 4; mi++) {
        size_t r0 = (size_t)blockIdx.y * 128 + warpM * 64 + mi * 16 + g;
        #pragma unroll
        for (int ni = 0; ni < 4; ni++) {
            int col = blockIdx.x * 128 + warpN * 32 + ni * 8 + tig * 2;
            if (CONVERT) {
                *(uint2*)((unsigned*)C + r0 * N + col) =
                    make_uint2(f2tf(acc[mi][ni][0] * oscale), f2tf(acc[mi][ni][1] * oscale));
                *(uint2*)((unsigned*)C + (r0 + 8) * N + col) =
                    make_uint2(f2tf(acc[mi][ni][2] * oscale), f2tf(acc[mi][ni][3] * oscale));
            } else {
                float b0 = bias[col], b1 = bias[col + 1];
                *(float2*)(C + r0 * N + col) =
                    make_float2(acc[mi][ni][0] + b0, acc[mi][ni][1] + b1);
                *(float2*)(C + (r0 + 8) * N + col) =
                    make_float2(acc[mi][ni][2] + b0, acc[mi][ni][3] + b1);
            }
        }
    }
}

// ----------------------------------------------------------------------------
// Flash attention (R10 passing version, unchanged): BQ=128, LDSM Q/K/P,
// scalar LDS V, cp.async double-buffered K/V. Inputs/outputs tf32 bits.
// ----------------------------------------------------------------------------
#define BQ 128
#define BK 64
#define LQ 68
#define LK 68
#define LV 72
#define LP 68

__global__ __launch_bounds__(256, 1) void fattn_kernel(
    const unsigned* __restrict__ Q, const unsigned* __restrict__ KV,
    const float* __restrict__ mask, unsigned* __restrict__ O)
{
    extern __shared__ unsigned sm[];
    unsigned* Qs = sm;
    unsigned* Ps = Qs + BQ * LQ;
    unsigned* Ks = Ps + BQ * LP;
    unsigned* Vs = Ks + 2 * BK * LK;
    float*    Msk = (float*)(Vs + 2 * BK * LV);

    int qb = blockIdx.x, h = blockIdx.y, b = blockIdx.z;
    int tid = threadIdx.x;
    int lane = tid & 31, wid = tid >> 5;
    int g = lane >> 2, tig = lane & 3;
    int warpRow = wid * 16;

    int mat = lane >> 3, l7 = lane & 7;
    int mrow = (mat & 1) * 8 + l7, mk4 = (mat >> 1) * 4;
    int nrow = (mat >> 1) * 8 + l7, nk4 = (mat & 1) * 4;

    const unsigned* KVbase = KV + (size_t)b * TSEQ * 2048 + h * 128;

    auto issueKV = [&](int kt, int st) {
        unsigned* Kst = Ks + st * BK * LK;
        unsigned* Vst = Vs + st * BK * LV;
        const unsigned* base = KVbase + (size_t)kt * BK * 2048;
        #pragma unroll
        for (int i2 = 0; i2 < 4; i2++) {
            int i = tid + i2 * 256;
            int row = i >> 4, c4 = (i & 15) << 2;
            const unsigned* kp = base + (size_t)row * 2048 + c4;
            cp16(&Kst[row * LK + c4], kp);
            cp16(&Vst[row * LV + c4], kp + 64);
        }
        cp_commit();
    };

    {
        const unsigned* Qbase = Q + (size_t)(b * TSEQ + qb * BQ) * DMM + h * DHD;
        #pragma unroll
        for (int i2 = 0; i2 < 8; i2++) {
            int i = tid + i2 * 256;
            int row = i >> 4, c4 = (i & 15) << 2;
            cp16(&Qs[row * LQ + c4], Qbase + (size_t)row * DMM + c4);
        }
        #pragma unroll
        for (int i2 = 0; i2 < 2; i2++) {
            int i = tid + i2 * 256;
            cp16((unsigned*)&Msk[i * 4], mask + (size_t)b * TSEQ + i * 4);
        }
    }
    issueKV(0, 0);

    float acc[8][4] = {};
    float m0 = -1e30f, m1 = -1e30f, l0 = 0.f, l1 = 0.f;
    const int NT = TSEQ / BK;

    for (int kt = 0; kt < NT; kt++) {
        int st = kt & 1;
        if (kt + 1 < NT) { issueKV(kt + 1, st ^ 1); cp_wait1(); }
        else             { cp_wait0(); }
        __syncthreads();

        unsigned* Kst = Ks + st * BK * LK;
        unsigned* Vst = Vs + st * BK * LV;

        float s[8][4] = {};
        #pragma unroll
        for (int ks = 0; ks < 8; ks++) {
            int kk = ks * 8;
            unsigned af[4], bk4[4][4];
            ldsm4(af, &Qs[(warpRow + mrow) * LQ + kk + mk4]);
            #pragma unroll
            for (int ntp = 0; ntp < 4; ntp++)
                ldsm4(bk4[ntp], &Kst[(ntp * 16 + nrow) * LK + kk + nk4]);
            #pragma unroll
            for (int nt = 0; nt < 8; nt++)
                mma_tf32(s[nt], af, &bk4[nt >> 1][(nt & 1) * 2]);
        }

        #pragma unroll
        for (int nt = 0; nt < 8; nt++) {
            int c0 = kt * BK + nt * 8 + tig * 2;
            if (Msk[c0] == 0.f)     { s[nt][0] = -1e30f; s[nt][2] = -1e30f; }
            if (Msk[c0 + 1] == 0.f) { s[nt][1] = -1e30f; s[nt][3] = -1e30f; }
        }

        float mx0 = -1e30f, mx1 = -1e30f;
        #pragma unroll
        for (int nt = 0; nt < 8; nt++) {
            mx0 = fmaxf(mx0, fmaxf(s[nt][0], s[nt][1]));
            mx1 = fmaxf(mx1, fmaxf(s[nt][2], s[nt][3]));
        }
        #pragma unroll
        for (int o = 1; o < 4; o <<= 1) {
            mx0 = fmaxf(mx0, __shfl_xor_sync(0xffffffffu, mx0, o));
            mx1 = fmaxf(mx1, __shfl_xor_sync(0xffffffffu, mx1, o));
        }
        float mn0 = fmaxf(m0, mx0), mn1 = fmaxf(m1, mx1);
        float cr0 = __expf(m0 - mn0), cr1 = __expf(m1 - mn1);
        float rs0 = 0.f, rs1 = 0.f;
        #pragma unroll
        for (int nt = 0; nt < 8; nt++) {
            s[nt][0] = __expf(s[nt][0] - mn0); rs0 += s[nt][0];
            s[nt][1] = __expf(s[nt][1] - mn0); rs0 += s[nt][1];
            s[nt][2] = __expf(s[nt][2] - mn1); rs1 += s[nt][2];
            s[nt][3] = __expf(s[nt][3] - mn1); rs1 += s[nt][3];
        }
        #pragma unroll
        for (int o = 1; o < 4; o <<= 1) {
            rs0 += __shfl_xor_sync(0xffffffffu, rs0, o);
            rs1 += __shfl_xor_sync(0xffffffffu, rs1, o);
        }
        l0 = l0 * cr0 + rs0;  m0 = mn0;
        l1 = l1 * cr1 + rs1;  m1 = mn1;
        #pragma unroll
        for (int nt = 0; nt < 8; nt++) {
            acc[nt][0] *= cr0; acc[nt][1] *= cr0;
            acc[nt][2] *= cr1; acc[nt][3] *= cr1;
        }

        #pragma unroll
        for (int nt = 0; nt < 8; nt++) {
            int colb = nt * 8 + tig * 2;
            *(uint2*)&Ps[(warpRow + g) * LP + colb] =
                make_uint2(f2tf(s[nt][0]), f2tf(s[nt][1]));
            *(uint2*)&Ps[(warpRow + g + 8) * LP + colb] =
                make_uint2(f2tf(s[nt][2]), f2tf(s[nt][3]));
        }
        __syncwarp();

        #pragma unroll
        for (int ks = 0; ks < 8; ks++) {
            int kk = ks * 8;
            unsigned af[4];
            ldsm4(af, &Ps[(warpRow + mrow) * LP + kk + mk4]);
            #pragma unroll
            for (int nt = 0; nt < 8; nt++) {
                unsigned bf[2];
                int c = nt * 8 + g;
                bf[0] = Vst[(kk + tig) * LV + c];
                bf[1] = Vst[(kk + tig + 4) * LV + c];
                mma_tf32(acc[nt], af, bf);
            }
        }
        __syncthreads();
    }

    float inv0 = 1.f / l0, inv1 = 1.f / l1;
    size_t row0 = (size_t)(b * TSEQ + qb * BQ + warpRow + g);
    #pragma unroll
    for (int nt = 0; nt < 8; nt++) {
        int col = h * DHD + nt * 8 + tig * 2;
        *(uint2*)(O + row0 * DMM + col) =
            make_uint2(f2tf(acc[nt][0] * inv0), f2tf(acc[nt][1] * inv0));
        *(uint2*)(O + (row0 + 8) * DMM + col) =
            make_uint2(f2tf(acc[nt][2] * inv1), f2tf(acc[nt][3] * inv1));
    }
}

// ----------------------------------------------------------------------------
extern "C" void kernel_launch(void* const* d_in, const int* in_sizes, int n_in,
                              void* d_out, int out_size)
{
    const float* x1   = (const float*)d_in[0];
    const float* x2   = (const float*)d_in[1];
    const float* mask = (const float*)d_in[2];
    const float* Wq   = (const float*)d_in[3];
    const float* Wkv  = (const float*)d_in[4];
    const float* Wo   = (const float*)d_in[5];
    const float* bo   = (const float*)d_in[6];
    float* out = (float*)d_out;

    unsigned *wqt, *wkvt, *wot, *q, *kv, *attn;
    cudaGetSymbolAddress((void**)&wqt, g_wqt);
    cudaGetSymbolAddress((void**)&wkvt, g_wkvt);
    cudaGetSymbolAddress((void**)&wot, g_wot);
    cudaGetSymbolAddress((void**)&q, g_q);
    cudaGetSymbolAddress((void**)&kv, g_kv);
    cudaGetSymbolAddress((void**)&attn, g_attn);

    dim3 blk(256);
    // Prep: transpose+cvt weights only (activations converted in-register)
    transpose_cvt_kernel<<<dim3(DMM / 32, DMM / 32), blk>>>(Wq, wqt, DMM, DMM);
    transpose_cvt_kernel<<<dim3(2 * DMM / 32, DMM / 32), blk>>>(Wkv, wkvt, DMM, 2 * DMM);
    transpose_cvt_kernel<<<dim3(DMM / 32, DMM / 32), blk>>>(Wo, wot, DMM, DMM);

    // Q proj: raw-fp32 A (fragment cvt), bits out pre-scaled 1/8
    tgemm_kernel<1, 1><<<dim3(DMM / 128, BT / 128), blk>>>(
        (const unsigned*)x1, wqt, (float*)q, BT, DMM, DMM, nullptr, 0.125f);
    // KV proj: raw-fp32 A, bits out
    tgemm_kernel<1, 1><<<dim3(2 * DMM / 128, BT / 128), blk>>>(
        (const unsigned*)x2, wkvt, (float*)kv, BT, 2 * DMM, DMM, nullptr, 1.0f);

    int smem_bytes = (BQ * LQ + BQ * LP + 2 * BK * LK + 2 * BK * LV + TSEQ)
                     * (int)sizeof(unsigned);
    cudaFuncSetAttribute(fattn_kernel, cudaFuncAttributeMaxDynamicSharedMemorySize, smem_bytes);
    fattn_kernel<<<dim3(TSEQ / BQ, HN, BATCH), blk, smem_bytes>>>(q, kv, mask, attn);

    // O proj: A is pre-converted bits (fattn epilogue), fp32 out + bias
    tgemm_kernel<0, 0><<<dim3(DMM / 128, BT / 128), blk>>>(
        attn, wot, out, BT, DMM, DMM, bo, 1.0f);
}

// round 15
// speedup vs baseline: 1.0400x; 1.0288x over previous
#include <cuda_runtime.h>

#define BT   8192   // B*T
#define DMM  1024
#define HN   16
#define DHD  64
#define TSEQ 2048
#define BATCH 4

// Scratch: tf32-RNA bit patterns.
__device__ unsigned g_x1c[BT * DMM];
__device__ unsigned g_x2c[BT * DMM];
__device__ unsigned g_wqt[DMM * DMM];        // Wq^T  [N][K]
__device__ unsigned g_wkvt[2 * DMM * DMM];   // Wkv^T [N][K]
__device__ unsigned g_wot[DMM * DMM];        // Wo^T  [N][K]
__device__ unsigned g_q[BT * DMM];           // Q proj (bits, pre-scaled 1/8)
__device__ unsigned g_kv[BT * 2 * DMM];      // KV proj (bits)
__device__ unsigned g_attn[BT * DMM];        // attention out (bits)

__device__ __forceinline__ void cp16(unsigned* smem, const void* gmem) {
    unsigned s = (unsigned)__cvta_generic_to_shared(smem);
    asm volatile("cp.async.cg.shared.global [%0], [%1], 16;\n" :: "r"(s), "l"(gmem));
}
__device__ __forceinline__ void cp_commit() {
    asm volatile("cp.async.commit_group;\n" ::: "memory");
}
__device__ __forceinline__ void cp_wait1() {
    asm volatile("cp.async.wait_group 1;\n" ::: "memory");
}
__device__ __forceinline__ void cp_wait0() {
    asm volatile("cp.async.wait_group 0;\n" ::: "memory");
}

__device__ __forceinline__ unsigned f2tf(float x) {
    unsigned r;
    asm("cvt.rna.tf32.f32 %0, %1;" : "=r"(r) : "f"(x));
    return r;
}

__device__ __forceinline__ void mma_tf32(float* d, const unsigned* a, const unsigned* b) {
    asm volatile(
        "mma.sync.aligned.m16n8k8.row.col.f32.tf32.tf32.f32 "
        "{%0,%1,%2,%3}, {%4,%5,%6,%7}, {%8,%9}, {%0,%1,%2,%3};\n"
        : "+f"(d[0]), "+f"(d[1]), "+f"(d[2]), "+f"(d[3])
        : "r"(a[0]), "r"(a[1]), "r"(a[2]), "r"(a[3]),
          "r"(b[0]), "r"(b[1]));
}

__device__ __forceinline__ void ldsm4(unsigned r[4], const unsigned* p) {
    unsigned a = (unsigned)__cvta_generic_to_shared(p);
    asm volatile("ldmatrix.sync.aligned.m8n8.x4.shared.b16 {%0,%1,%2,%3}, [%4];"
        : "=r"(r[0]), "=r"(r[1]), "=r"(r[2]), "=r"(r[3]) : "r"(a));
}

// ----------------------------------------------------------------------------
// Prep kernels.
// cvt_kernel: 8 independent float4 per thread (MLP=8) -> streaming at HBM rate.
// ----------------------------------------------------------------------------
__global__ __launch_bounds__(256) void cvt_kernel(
    const float4* __restrict__ src, uint4* __restrict__ dst)
{
    int base = blockIdx.x * 2048 + threadIdx.x;   // 8 vec4 per thread, stride 256
    float4 v[8];
    #pragma unroll
    for (int j = 0; j < 8; j++) v[j] = src[base + j * 256];
    #pragma unroll
    for (int j = 0; j < 8; j++)
        dst[base + j * 256] = make_uint4(f2tf(v[j].x), f2tf(v[j].y),
                                         f2tf(v[j].z), f2tf(v[j].w));
}

__global__ __launch_bounds__(256) void transpose_cvt_kernel(
    const float* __restrict__ W, unsigned* __restrict__ Wt, int K, int N)
{
    __shared__ unsigned t[32][33];
    int bn = blockIdx.x * 32, bk = blockIdx.y * 32;
    int tx = threadIdx.x & 31, ty = threadIdx.x >> 5;
    #pragma unroll
    for (int i = ty; i < 32; i += 8)
        t[tx][i] = f2tf(W[(size_t)(bk + i) * N + bn + tx]);
    __syncthreads();
    #pragma unroll
    for (int i = ty; i < 32; i += 8)
        Wt[(size_t)(bn + i) * K + bk + tx] = t[i][tx];
}

// ----------------------------------------------------------------------------
// TF32 GEMM (R10 structure, unchanged): CTA 128x128, BK=16, 8 warps (2x4),
// warp 64x32, LDSM fragments, zero in-loop cvt, cp.async double-buffered.
// ----------------------------------------------------------------------------
#define LD20 20

__global__ __launch_bounds__(256, 2) void tgemm_kernel(
    const unsigned* __restrict__ A, const unsigned* __restrict__ Bt,
    float* __restrict__ C, int M, int N, int K, const float* __restrict__ bias,
    float oscale, int convert)
{
    __shared__ unsigned As[2][128 * LD20];
    __shared__ unsigned Bs[2][128 * LD20];
    int tid = threadIdx.x;
    int lane = tid & 31, wid = tid >> 5;
    int g = lane >> 2, tig = lane & 3;
    int warpM = wid & 1, warpN = wid >> 1;

    int mat = lane >> 3, l7 = lane & 7;
    int mrow = (mat & 1) * 8 + l7, mk4 = (mat >> 1) * 4;
    int nrow = (mat >> 1) * 8 + l7, nk4 = (mat & 1) * 4;

    const unsigned* Ap = A + (size_t)blockIdx.y * 128 * K;
    const unsigned* Bp = Bt + (size_t)blockIdx.x * 128 * K;

    float acc[4][4][4] = {};
    int av0 = tid, av1 = tid + 256;
    int r0v = av0 >> 2, c0v = (av0 & 3) * 4;
    int r1v = av1 >> 2, c1v = (av1 & 3) * 4;

    auto issueTile = [&](int k0, int st) {
        cp16(&As[st][r0v * LD20 + c0v], Ap + (size_t)r0v * K + k0 + c0v);
        cp16(&As[st][r1v * LD20 + c1v], Ap + (size_t)r1v * K + k0 + c1v);
        cp16(&Bs[st][r0v * LD20 + c0v], Bp + (size_t)r0v * K + k0 + c0v);
        cp16(&Bs[st][r1v * LD20 + c1v], Bp + (size_t)r1v * K + k0 + c1v);
        cp_commit();
    };

    int NIT = K >> 4;
    issueTile(0, 0);

    for (int it = 0; it < NIT; it++) {
        int st = it & 1;
        if (it + 1 < NIT) { issueTile((it + 1) << 4, st ^ 1); cp_wait1(); }
        else              { cp_wait0(); }
        __syncthreads();

        #pragma unroll
        for (int ks = 0; ks < 2; ks++) {
            int kk = ks * 8;
            unsigned af[4][4], bf[2][4];
            #pragma unroll
            for (int mi = 0; mi < 4; mi++)
                ldsm4(af[mi], &As[st][(warpM * 64 + mi * 16 + mrow) * LD20 + kk + mk4]);
            #pragma unroll
            for (int nip = 0; nip < 2; nip++)
                ldsm4(bf[nip], &Bs[st][(warpN * 32 + nip * 16 + nrow) * LD20 + kk + nk4]);
            #pragma unroll
            for (int mi = 0; mi < 4; mi++)
                #pragma unroll
                for (int ni = 0; ni < 4; ni++)
                    mma_tf32(acc[mi][ni], af[mi], &bf[ni >> 1][(ni & 1) * 2]);
        }
        __syncthreads();
    }

    #pragma unroll
    for (int mi = 0; mi < 4; mi++) {
        size_t r0 = (size_t)blockIdx.y * 128 + warpM * 64 + mi * 16 + g;
        #pragma unroll
        for (int ni = 0; ni < 4; ni++) {
            int col = blockIdx.x * 128 + warpN * 32 + ni * 8 + tig * 2;
            if (convert) {
                *(uint2*)((unsigned*)C + r0 * N + col) =
                    make_uint2(f2tf(acc[mi][ni][0] * oscale), f2tf(acc[mi][ni][1] * oscale));
                *(uint2*)((unsigned*)C + (r0 + 8) * N + col) =
                    make_uint2(f2tf(acc[mi][ni][2] * oscale), f2tf(acc[mi][ni][3] * oscale));
            } else {
                float b0 = bias[col], b1 = bias[col + 1];
                *(float2*)(C + r0 * N + col) =
                    make_float2(acc[mi][ni][0] + b0, acc[mi][ni][1] + b1);
                *(float2*)(C + (r0 + 8) * N + col) =
                    make_float2(acc[mi][ni][2] + b0, acc[mi][ni][3] + b1);
            }
        }
    }
}

// ----------------------------------------------------------------------------
// Flash attention (R10 passing version, unchanged).
// ----------------------------------------------------------------------------
#define BQ 128
#define BK 64
#define LQ 68
#define LK 68
#define LV 72
#define LP 68

__global__ __launch_bounds__(256, 1) void fattn_kernel(
    const unsigned* __restrict__ Q, const unsigned* __restrict__ KV,
    const float* __restrict__ mask, unsigned* __restrict__ O)
{
    extern __shared__ unsigned sm[];
    unsigned* Qs = sm;
    unsigned* Ps = Qs + BQ * LQ;
    unsigned* Ks = Ps + BQ * LP;
    unsigned* Vs = Ks + 2 * BK * LK;
    float*    Msk = (float*)(Vs + 2 * BK * LV);

    int qb = blockIdx.x, h = blockIdx.y, b = blockIdx.z;
    int tid = threadIdx.x;
    int lane = tid & 31, wid = tid >> 5;
    int g = lane >> 2, tig = lane & 3;
    int warpRow = wid * 16;

    int mat = lane >> 3, l7 = lane & 7;
    int mrow = (mat & 1) * 8 + l7, mk4 = (mat >> 1) * 4;
    int nrow = (mat >> 1) * 8 + l7, nk4 = (mat & 1) * 4;

    const unsigned* KVbase = KV + (size_t)b * TSEQ * 2048 + h * 128;

    auto issueKV = [&](int kt, int st) {
        unsigned* Kst = Ks + st * BK * LK;
        unsigned* Vst = Vs + st * BK * LV;
        const unsigned* base = KVbase + (size_t)kt * BK * 2048;
        #pragma unroll
        for (int i2 = 0; i2 < 4; i2++) {
            int i = tid + i2 * 256;
            int row = i >> 4, c4 = (i & 15) << 2;
            const unsigned* kp = base + (size_t)row * 2048 + c4;
            cp16(&Kst[row * LK + c4], kp);
            cp16(&Vst[row * LV + c4], kp + 64);
        }
        cp_commit();
    };

    {
        const unsigned* Qbase = Q + (size_t)(b * TSEQ + qb * BQ) * DMM + h * DHD;
        #pragma unroll
        for (int i2 = 0; i2 < 8; i2++) {
            int i = tid + i2 * 256;
            int row = i >> 4, c4 = (i & 15) << 2;
            cp16(&Qs[row * LQ + c4], Qbase + (size_t)row * DMM + c4);
        }
        #pragma unroll
        for (int i2 = 0; i2 < 2; i2++) {
            int i = tid + i2 * 256;
            cp16((unsigned*)&Msk[i * 4], mask + (size_t)b * TSEQ + i * 4);
        }
    }
    issueKV(0, 0);

    float acc[8][4] = {};
    float m0 = -1e30f, m1 = -1e30f, l0 = 0.f, l1 = 0.f;
    const int NT = TSEQ / BK;

    for (int kt = 0; kt < NT; kt++) {
        int st = kt & 1;
        if (kt + 1 < NT) { issueKV(kt + 1, st ^ 1); cp_wait1(); }
        else             { cp_wait0(); }
        __syncthreads();

        unsigned* Kst = Ks + st * BK * LK;
        unsigned* Vst = Vs + st * BK * LV;

        float s[8][4] = {};
        #pragma unroll
        for (int ks = 0; ks < 8; ks++) {
            int kk = ks * 8;
            unsigned af[4], bk4[4][4];
            ldsm4(af, &Qs[(warpRow + mrow) * LQ + kk + mk4]);
            #pragma unroll
            for (int ntp = 0; ntp < 4; ntp++)
                ldsm4(bk4[ntp], &Kst[(ntp * 16 + nrow) * LK + kk + nk4]);
            #pragma unroll
            for (int nt = 0; nt < 8; nt++)
                mma_tf32(s[nt], af, &bk4[nt >> 1][(nt & 1) * 2]);
        }

        #pragma unroll
        for (int nt = 0; nt < 8; nt++) {
            int c0 = kt * BK + nt * 8 + tig * 2;
            if (Msk[c0] == 0.f)     { s[nt][0] = -1e30f; s[nt][2] = -1e30f; }
            if (Msk[c0 + 1] == 0.f) { s[nt][1] = -1e30f; s[nt][3] = -1e30f; }
        }

        float mx0 = -1e30f, mx1 = -1e30f;
        #pragma unroll
        for (int nt = 0; nt < 8; nt++) {
            mx0 = fmaxf(mx0, fmaxf(s[nt][0], s[nt][1]));
            mx1 = fmaxf(mx1, fmaxf(s[nt][2], s[nt][3]));
        }
        #pragma unroll
        for (int o = 1; o < 4; o <<= 1) {
            mx0 = fmaxf(mx0, __shfl_xor_sync(0xffffffffu, mx0, o));
            mx1 = fmaxf(mx1, __shfl_xor_sync(0xffffffffu, mx1, o));
        }
        float mn0 = fmaxf(m0, mx0), mn1 = fmaxf(m1, mx1);
        float cr0 = __expf(m0 - mn0), cr1 = __expf(m1 - mn1);
        float rs0 = 0.f, rs1 = 0.f;
        #pragma unroll
        for (int nt = 0; nt < 8; nt++) {
            s[nt][0] = __expf(s[nt][0] - mn0); rs0 += s[nt][0];
            s[nt][1] = __expf(s[nt][1] - mn0); rs0 += s[nt][1];
            s[nt][2] = __expf(s[nt][2] - mn1); rs1 += s[nt][2];
            s[nt][3] = __expf(s[nt][3] - mn1); rs1 += s[nt][3];
        }
        #pragma unroll
        for (int o = 1; o < 4; o <<= 1) {
            rs0 += __shfl_xor_sync(0xffffffffu, rs0, o);
            rs1 += __shfl_xor_sync(0xffffffffu, rs1, o);
        }
        l0 = l0 * cr0 + rs0;  m0 = mn0;
        l1 = l1 * cr1 + rs1;  m1 = mn1;
        #pragma unroll
        for (int nt = 0; nt < 8; nt++) {
            acc[nt][0] *= cr0; acc[nt][1] *= cr0;
            acc[nt][2] *= cr1; acc[nt][3] *= cr1;
        }

        #pragma unroll
        for (int nt = 0; nt < 8; nt++) {
            int colb = nt * 8 + tig * 2;
            *(uint2*)&Ps[(warpRow + g) * LP + colb] =
                make_uint2(f2tf(s[nt][0]), f2tf(s[nt][1]));
            *(uint2*)&Ps[(warpRow + g + 8) * LP + colb] =
                make_uint2(f2tf(s[nt][2]), f2tf(s[nt][3]));
        }
        __syncwarp();

        #pragma unroll
        for (int ks = 0; ks < 8; ks++) {
            int kk = ks * 8;
            unsigned af[4];
            ldsm4(af, &Ps[(warpRow + mrow) * LP + kk + mk4]);
            #pragma unroll
            for (int nt = 0; nt < 8; nt++) {
                unsigned bf[2];
                int c = nt * 8 + g;
                bf[0] = Vst[(kk + tig) * LV + c];
                bf[1] = Vst[(kk + tig + 4) * LV + c];
                mma_tf32(acc[nt], af, bf);
            }
        }
        __syncthreads();
    }

    float inv0 = 1.f / l0, inv1 = 1.f / l1;
    size_t row0 = (size_t)(b * TSEQ + qb * BQ + warpRow + g);
    #pragma unroll
    for (int nt = 0; nt < 8; nt++) {
        int col = h * DHD + nt * 8 + tig * 2;
        *(uint2*)(O + row0 * DMM + col) =
            make_uint2(f2tf(acc[nt][0] * inv0), f2tf(acc[nt][1] * inv0));
        *(uint2*)(O + (row0 + 8) * DMM + col) =
            make_uint2(f2tf(acc[nt][2] * inv1), f2tf(acc[nt][3] * inv1));
    }
}

// ----------------------------------------------------------------------------
extern "C" void kernel_launch(void* const* d_in, const int* in_sizes, int n_in,
                              void* d_out, int out_size)
{
    const float* x1   = (const float*)d_in[0];
    const float* x2   = (const float*)d_in[1];
    const float* mask = (const float*)d_in[2];
    const float* Wq   = (const float*)d_in[3];
    const float* Wkv  = (const float*)d_in[4];
    const float* Wo   = (const float*)d_in[5];
    const float* bo   = (const float*)d_in[6];
    float* out = (float*)d_out;

    unsigned *x1c, *x2c, *wqt, *wkvt, *wot, *q, *kv, *attn;
    cudaGetSymbolAddress((void**)&x1c, g_x1c);
    cudaGetSymbolAddress((void**)&x2c, g_x2c);
    cudaGetSymbolAddress((void**)&wqt, g_wqt);
    cudaGetSymbolAddress((void**)&wkvt, g_wkvt);
    cudaGetSymbolAddress((void**)&wot, g_wot);
    cudaGetSymbolAddress((void**)&q, g_q);
    cudaGetSymbolAddress((void**)&kv, g_kv);
    cudaGetSymbolAddress((void**)&attn, g_attn);

    dim3 blk(256);
    // Prep: high-MLP streaming cvt (2M vec4 each -> 1024 blocks x 8 vec4/thread)
    cvt_kernel<<<BT * DMM / 8192, blk>>>((const float4*)x1, (uint4*)x1c);
    cvt_kernel<<<BT * DMM / 8192, blk>>>((const float4*)x2, (uint4*)x2c);
    transpose_cvt_kernel<<<dim3(DMM / 32, DMM / 32), blk>>>(Wq, wqt, DMM, DMM);
    transpose_cvt_kernel<<<dim3(2 * DMM / 32, DMM / 32), blk>>>(Wkv, wkvt, DMM, 2 * DMM);
    transpose_cvt_kernel<<<dim3(DMM / 32, DMM / 32), blk>>>(Wo, wot, DMM, DMM);

    // Projections (R10 LDSM kernels)
    tgemm_kernel<<<dim3(DMM / 128, BT / 128), blk>>>(
        x1c, wqt, (float*)q, BT, DMM, DMM, nullptr, 0.125f, 1);
    tgemm_kernel<<<dim3(2 * DMM / 128, BT / 128), blk>>>(
        x2c, wkvt, (float*)kv, BT, 2 * DMM, DMM, nullptr, 1.0f, 1);

    int smem_bytes = (BQ * LQ + BQ * LP + 2 * BK * LK + 2 * BK * LV + TSEQ)
                     * (int)sizeof(unsigned);
    cudaFuncSetAttribute(fattn_kernel, cudaFuncAttributeMaxDynamicSharedMemorySize, smem_bytes);
    fattn_kernel<<<dim3(TSEQ / BQ, HN, BATCH), blk, smem_bytes>>>(q, kv, mask, attn);

    tgemm_kernel<<<dim3(DMM / 128, BT / 128), blk>>>(
        attn, wot, out, BT, DMM, DMM, bo, 1.0f, 0);
}